// round 2
// baseline (speedup 1.0000x reference)
#include <cuda_runtime.h>

#define HH 40
#define WW 128
#define PP 5120
#define CC 128
#define KKN 25
#define SPOTN 5
#define NEGV (-1e8f)
#define FMAXV 3.402823466e38f

// ---------------- scratch (device globals; no allocations allowed) ----------
__device__ float g_nimf[PP*CC];
__device__ float g_npcf[PP*CC];
__device__ int   g_nb[PP*KKN];
__device__ unsigned long long g_rowbest[PP];
__device__ unsigned long long g_colbest[PP];
__device__ float g_imbs[PP];   // best_score per pixel
__device__ int   g_imbi[PP];   // best_index per pixel (pc idx)
__device__ float g_pcbs[PP];   // best_pc_score per point
__device__ int   g_pcbi[PP];   // best_pc_idx per point (pixel idx)
__device__ int   g_spot_im[PP*125];
__device__ int   g_spot_pc[PP*125];

__device__ __forceinline__ unsigned f2sort(float f){
    unsigned b = __float_as_uint(f);
    return (b & 0x80000000u) ? ~b : (b | 0x80000000u);
}
__device__ __forceinline__ float sort2f(unsigned u){
    unsigned b = (u & 0x80000000u) ? (u & 0x7fffffffu) : ~u;
    return __uint_as_float(b);
}
__device__ __forceinline__ int iclamp(int v, int lo, int hi){
    return v < lo ? lo : (v > hi ? hi : v);
}
__device__ __forceinline__ unsigned long long maxull(unsigned long long a, unsigned long long b){
    return a > b ? a : b;
}
#define KEYPACK(v,n) ((((unsigned long long)f2sort(v)) << 32) | (unsigned)(~(n)))

// ---------------- K1: L2 normalize both feature sets ------------------------
__global__ __launch_bounds__(256) void k_norm(const float* __restrict__ imf,
                                              const float* __restrict__ pcf){
    int warp = (blockIdx.x*blockDim.x + threadIdx.x) >> 5;
    int lane = threadIdx.x & 31;
    if (warp >= 2*PP) return;
    const float* src = (warp < PP) ? imf : pcf;
    float* dst       = (warp < PP) ? g_nimf : g_npcf;
    int r = (warp < PP) ? warp : warp - PP;
    float4 v = ((const float4*)(src + (size_t)r*CC))[lane];
    float ss = v.x*v.x + v.y*v.y + v.z*v.z + v.w*v.w;
    #pragma unroll
    for (int o=16;o;o>>=1) ss += __shfl_xor_sync(0xffffffffu, ss, o);
    float inv = 1.0f / fmaxf(sqrtf(ss), 1e-12f);
    v.x*=inv; v.y*=inv; v.z*=inv; v.w*=inv;
    ((float4*)(dst + (size_t)r*CC))[lane] = v;
}

// ---------------- K2: init packed argmax accumulators -----------------------
__global__ void k_init(){
    int i = blockIdx.x*blockDim.x + threadIdx.x;
    if (i < PP){ g_rowbest[i] = 0ull; g_colbest[i] = 0ull; }
}

// ---------------- K3: knn (top-25 nearest, self first, tie->lower idx) ------
__global__ __launch_bounds__(256) void k_knn(const float* __restrict__ pts){
    __shared__ unsigned long long dist[PP];
    __shared__ unsigned long long red[256];
    int i = blockIdx.x;
    int tid = threadIdx.x;
    float px = pts[i*3+0], py = pts[i*3+1], pz = pts[i*3+2];
    for (int j=tid; j<PP; j+=256){
        float dx = pts[j*3+0]-px, dy = pts[j*3+1]-py, dz = pts[j*3+2]-pz;
        float d2 = dx*dx + dy*dy + dz*dz;   // >=0, bit order == numeric order
        dist[j] = ((unsigned long long)__float_as_uint(d2) << 32) | (unsigned)j;
    }
    __syncthreads();
    unsigned long long lmin = ~0ull;
    for (int j=tid; j<PP; j+=256){ unsigned long long d = dist[j]; if (d < lmin) lmin = d; }
    for (int t=0; t<KKN; t++){
        red[tid] = lmin;
        __syncthreads();
        for (int s=128; s; s>>=1){
            if (tid < s){ if (red[tid+s] < red[tid]) red[tid] = red[tid+s]; }
            __syncthreads();
        }
        unsigned long long best = red[0];
        __syncthreads();
        int j = (int)(unsigned)best;
        if (tid == 0) g_nb[i*KKN + t] = j;
        if ((j & 255) == tid){
            dist[j] = ~0ull;
            lmin = ~0ull;
            for (int jj=tid; jj<PP; jj+=256){ unsigned long long d = dist[jj]; if (d < lmin) lmin = d; }
        }
    }
}

// ---------------- K4: fused GEMM + row/col argmax ----------------------------
// S[p][n] = dot(nimf[p], npcf[n]); row max -> g_rowbest, col max -> g_colbest.
// Accumulators are 16 NAMED float4 registers (no local arrays, no address-of).
#define FOR_ROWS(OP) OP(0,d0a,d0b) OP(1,d1a,d1b) OP(2,d2a,d2b) OP(3,d3a,d3b) \
                     OP(4,d4a,d4b) OP(5,d5a,d5b) OP(6,d6a,d6b) OP(7,d7a,d7b)
#define DECL_ROW(r,A,B) float4 A = {0.f,0.f,0.f,0.f}; float4 B = {0.f,0.f,0.f,0.f};
#define AV0 a0.x
#define AV1 a0.y
#define AV2 a0.z
#define AV3 a0.w
#define AV4 a1.x
#define AV5 a1.y
#define AV6 a1.z
#define AV7 a1.w
#define FMA_ROW(r,A,B) { float av_ = AV##r; \
    A.x = fmaf(av_, b0.x, A.x); A.y = fmaf(av_, b0.y, A.y); \
    A.z = fmaf(av_, b0.z, A.z); A.w = fmaf(av_, b0.w, A.w); \
    B.x = fmaf(av_, b1.x, B.x); B.y = fmaf(av_, b1.y, B.y); \
    B.z = fmaf(av_, b1.z, B.z); B.w = fmaf(av_, b1.w, B.w); }
#define ROW_ST(r,A,B) { int n0_ = c0 + tx*8; \
    unsigned long long bb_ = KEYPACK(A.x, n0_); \
    bb_ = maxull(bb_, KEYPACK(A.y, n0_+1)); bb_ = maxull(bb_, KEYPACK(A.z, n0_+2)); \
    bb_ = maxull(bb_, KEYPACK(A.w, n0_+3)); bb_ = maxull(bb_, KEYPACK(B.x, n0_+4)); \
    bb_ = maxull(bb_, KEYPACK(B.y, n0_+5)); bb_ = maxull(bb_, KEYPACK(B.z, n0_+6)); \
    bb_ = maxull(bb_, KEYPACK(B.w, n0_+7)); \
    red[(ty*8+r)*16 + tx] = bb_; }
#define COL_UPD(r,A,B) { int m_ = r0 + ty*8 + r; \
    e0 = maxull(e0, KEYPACK(A.x, m_)); e1 = maxull(e1, KEYPACK(A.y, m_)); \
    e2 = maxull(e2, KEYPACK(A.z, m_)); e3 = maxull(e3, KEYPACK(A.w, m_)); \
    e4 = maxull(e4, KEYPACK(B.x, m_)); e5 = maxull(e5, KEYPACK(B.y, m_)); \
    e6 = maxull(e6, KEYPACK(B.z, m_)); e7 = maxull(e7, KEYPACK(B.w, m_)); }

__global__ __launch_bounds__(256) void k_gemm(){
    __shared__ __align__(16) char smem_raw[2*32*132*4];  // 33792 B
    float (*As)[132] = (float (*)[132])smem_raw;
    float (*Bs)[132] = (float (*)[132])(smem_raw + 32*132*4);
    int tid = threadIdx.x;
    int tx = tid & 15, ty = tid >> 4;
    int r0 = blockIdx.y*128, c0 = blockIdx.x*128;
    FOR_ROWS(DECL_ROW)

    for (int kc=0; kc<CC; kc+=32){
        #pragma unroll
        for (int it=0; it<4; ++it){
            int idx = it*256 + tid;
            int row = idx >> 3;
            int k4  = (idx & 7)*4;
            float4 a = *(const float4*)&g_nimf[(size_t)(r0+row)*CC + kc + k4];
            As[k4+0][row]=a.x; As[k4+1][row]=a.y; As[k4+2][row]=a.z; As[k4+3][row]=a.w;
            float4 b = *(const float4*)&g_npcf[(size_t)(c0+row)*CC + kc + k4];
            Bs[k4+0][row]=b.x; Bs[k4+1][row]=b.y; Bs[k4+2][row]=b.z; Bs[k4+3][row]=b.w;
        }
        __syncthreads();
        #pragma unroll 8
        for (int k=0; k<32; k++){
            float4 a0 = *(const float4*)&As[k][ty*8+0];
            float4 a1 = *(const float4*)&As[k][ty*8+4];
            float4 b0 = *(const float4*)&Bs[k][tx*8+0];
            float4 b1 = *(const float4*)&Bs[k][tx*8+4];
            FOR_ROWS(FMA_ROW)
        }
        __syncthreads();
    }

    unsigned long long* red = (unsigned long long*)smem_raw;  // 2048 entries
    // ---- row argmax (index = point n, tie -> lower n) ----
    FOR_ROWS(ROW_ST)
    __syncthreads();
    if (tid < 128){
        unsigned long long b = 0ull;
        #pragma unroll
        for (int t=0;t<16;t++) b = maxull(b, red[tid*16+t]);
        atomicMax(&g_rowbest[r0+tid], b);
    }
    __syncthreads();
    // ---- col argmax (index = pixel p, tie -> lower p) ----
    unsigned long long e0=0,e1=0,e2=0,e3=0,e4=0,e5=0,e6=0,e7=0;
    FOR_ROWS(COL_UPD)
    red[(tx*8+0)*16 + ty] = e0;
    red[(tx*8+1)*16 + ty] = e1;
    red[(tx*8+2)*16 + ty] = e2;
    red[(tx*8+3)*16 + ty] = e3;
    red[(tx*8+4)*16 + ty] = e4;
    red[(tx*8+5)*16 + ty] = e5;
    red[(tx*8+6)*16 + ty] = e6;
    red[(tx*8+7)*16 + ty] = e7;
    __syncthreads();
    if (tid < 128){
        unsigned long long b = 0ull;
        #pragma unroll
        for (int t=0;t<16;t++) b = maxull(b, red[tid*16+t]);
        atomicMax(&g_colbest[c0+tid], b);
    }
}

// ---------------- K5: unpack packed argmax ----------------------------------
__global__ void k_unpack(){
    int i = blockIdx.x*blockDim.x + threadIdx.x;
    if (i >= PP) return;
    unsigned long long k1 = g_rowbest[i];
    g_imbs[i] = sort2f((unsigned)(k1 >> 32));
    g_imbi[i] = (int)(~(unsigned)k1);
    unsigned long long k2 = g_colbest[i];
    g_pcbs[i] = sort2f((unsigned)(k2 >> 32));
    g_pcbi[i] = (int)(~(unsigned)k2);
}

// ---------------- K6: im branch: sims, softmax, select out, top-4, spot -----
__global__ __launch_bounds__(128) void k_impix(float* __restrict__ sel_out){
    int warp = (blockIdx.x*blockDim.x + threadIdx.x) >> 5;
    int lane = threadIdx.x & 31;
    if (warp >= PP) return;
    int p = warp, h = p >> 7, w = p & 127;   // WW == 128
    float4 cf = ((const float4*)(g_nimf + (size_t)p*CC))[lane];

    float myval = 0.f;
    #pragma unroll 1
    for (int k=0; k<KKN; k++){
        int di = k/5 - 2, dj = k%5 - 2;
        int hh = iclamp(h+di, 0, HH-1), ww = iclamp(w+dj, 0, WW-1);
        float4 nf = ((const float4*)(g_nimf + (size_t)(hh*WW+ww)*CC))[lane];
        float s = cf.x*nf.x + cf.y*nf.y + cf.z*nf.z + cf.w*nf.w;
        #pragma unroll
        for (int o=16;o;o>>=1) s += __shfl_xor_sync(0xffffffffu, s, o);
        if (lane == k) myval = s;
    }
    // softmax over lanes 0..24
    float v = (lane < KKN) ? myval : -FMAXV;
    float m = v;
    #pragma unroll
    for (int o=16;o;o>>=1) m = fmaxf(m, __shfl_xor_sync(0xffffffffu, m, o));
    float e = (lane < KKN) ? expf(v - m) : 0.f;
    float su = e;
    #pragma unroll
    for (int o=16;o;o>>=1) su += __shfl_xor_sync(0xffffffffu, su, o);
    float soft = e / su;

    int di = lane/5 - 2, dj = lane%5 - 2;
    float selv = NEGV;
    if (lane < KKN){
        bool inb = ((unsigned)(h+di) < (unsigned)HH) && ((unsigned)(w+dj) < (unsigned)WW);
        int hh = iclamp(h+di, 0, HH-1), ww = iclamp(w+dj, 0, WW-1);
        float conf = g_imbs[hh*WW+ww];
        selv = inb ? soft*conf : NEGV;
        sel_out[(size_t)lane*PP + p] = selv;
    }
    // seeding: center (k=12) then top-4 excluding center; process immediately
    float cand = (lane < KKN && lane != 12) ? selv : -FMAXV;
    #pragma unroll 1
    for (int s=0; s<SPOTN; s++){
        int kk;
        if (s == 0){
            kk = 12;
        } else {
            unsigned long long key = ((unsigned long long)f2sort(cand) << 32) | (unsigned)(31 - lane);
            #pragma unroll
            for (int o=16;o;o>>=1){
                unsigned long long ok = __shfl_xor_sync(0xffffffffu, key, o);
                if (ok > key) key = ok;
            }
            kk = 31 - (int)(key & 0xffffffffull);
            if (lane == kk) cand = -FMAXV;
        }
        int q = (h + kk/5 - 2)*WW + (w + kk%5 - 2);  // selected are always in-bounds
        int sd = g_imbi[q];
        if (lane < KKN) g_spot_im[(size_t)p*125 + s*25 + lane] = g_nb[sd*KKN + lane];
    }
}

// ---------------- K7: pc branch ---------------------------------------------
__global__ __launch_bounds__(128) void k_pcpoint(){
    int warp = (blockIdx.x*blockDim.x + threadIdx.x) >> 5;
    int lane = threadIdx.x & 31;
    if (warp >= PP) return;
    int p = warp;
    float4 cf = ((const float4*)(g_npcf + (size_t)p*CC))[lane];

    float myval = 0.f; int myq = 0;
    #pragma unroll 1
    for (int k=0; k<KKN; k++){
        int q = g_nb[p*KKN + k];
        float4 nf = ((const float4*)(g_npcf + (size_t)q*CC))[lane];
        float s = cf.x*nf.x + cf.y*nf.y + cf.z*nf.z + cf.w*nf.w;
        #pragma unroll
        for (int o=16;o;o>>=1) s += __shfl_xor_sync(0xffffffffu, s, o);
        if (lane == k){ myval = s; myq = q; }
    }
    float v = (lane < KKN) ? myval : -FMAXV;
    float m = v;
    #pragma unroll
    for (int o=16;o;o>>=1) m = fmaxf(m, __shfl_xor_sync(0xffffffffu, m, o));
    float e = (lane < KKN) ? expf(v - m) : 0.f;
    float su = e;
    #pragma unroll
    for (int o=16;o;o>>=1) su += __shfl_xor_sync(0xffffffffu, su, o);
    float soft = e / su;

    float selv = NEGV;
    if (lane < KKN) selv = (lane == 0) ? NEGV : soft * g_pcbs[myq];
    float cand = (lane >= 1 && lane < KKN) ? selv : -FMAXV;
    #pragma unroll 1
    for (int s=0; s<SPOTN; s++){
        int kk;
        if (s == 0){
            kk = 0;
        } else {
            unsigned long long key = ((unsigned long long)f2sort(cand) << 32) | (unsigned)(31 - lane);
            #pragma unroll
            for (int o=16;o;o>>=1){
                unsigned long long ok = __shfl_xor_sync(0xffffffffu, key, o);
                if (ok > key) key = ok;
            }
            kk = 31 - (int)(key & 0xffffffffull);
            if (lane == kk) cand = -FMAXV;
        }
        int qq = __shfl_sync(0xffffffffu, myq, kk);
        int pix = g_pcbi[qq];
        int pr = pix >> 7, pc = pix & 127;
        if (lane < KKN){
            int rr = iclamp(pr + lane/5 - 2, 0, HH-1);
            int cc = iclamp(pc + lane%5 - 2, 0, WW-1);
            g_spot_pc[(size_t)p*125 + s*25 + lane] = rr*WW + cc;
        }
    }
}

// ---------------- K8: scatter mask + stable top-125 (bitmask scan) ----------
// which: 0 -> g_spot_im, 1 -> g_spot_pc (device-global pointers bound in-kernel)
__global__ __launch_bounds__(256) void k_mask(int which,
                                              float* __restrict__ omask,
                                              float* __restrict__ oidx){
    __shared__ unsigned bm[32][160];   // 32 rows x 5120 bits
    const int* spot = which ? g_spot_pc : g_spot_im;
    int r0 = blockIdx.x*32;
    int tid = threadIdx.x;
    for (int i=tid; i<32*160; i+=256) ((unsigned*)bm)[i] = 0u;
    __syncthreads();
    for (int e=tid; e<32*125; e+=256){
        int row = e / 125;
        int v = spot[(size_t)(r0+row)*125 + (e % 125)];
        atomicOr(&bm[row][v>>5], 1u << (v & 31));
    }
    __syncthreads();
    if (tid < 32){
        int row = tid, t = 0;
        float* om = omask + (size_t)(r0+row)*125;
        float* oi = oidx  + (size_t)(r0+row)*125;
        for (int w2=0; w2<160; w2++){
            unsigned x = bm[row][w2];
            while (x){
                int b = __ffs(x) - 1; x &= x - 1;
                oi[t] = (float)(w2*32 + b); om[t] = 1.f; t++;
            }
        }
        for (int j=0; t<125; j++){
            if (!((bm[row][j>>5] >> (j&31)) & 1u)){
                oi[t] = (float)j; om[t] = 0.f; t++;
            }
        }
    }
}

// ---------------- launch ------------------------------------------------------
extern "C" void kernel_launch(void* const* d_in, const int* in_sizes, int n_in,
                              void* d_out, int out_size){
    const float* imf = (const float*)d_in[0];
    const float* pcf = (const float*)d_in[1];
    const float* pts = (const float*)d_in[2];
    float* out = (float*)d_out;

    float* sel_out     = out;                       // 25*5120
    float* mask_out    = out + 25*PP;               // 5120*125
    float* idx_out     = out + 25*PP + 125*PP;      // 5120*125
    float* idx_pc_out  = out + 25*PP + 2*125*PP;    // 5120*125
    float* mask_pc_out = out + 25*PP + 3*125*PP;    // 5120*125

    k_norm<<<(2*PP*32 + 255)/256, 256>>>(imf, pcf);
    k_init<<<(PP+255)/256, 256>>>();
    k_knn<<<PP, 256>>>(pts);
    dim3 gg(PP/128, PP/128);
    k_gemm<<<gg, 256>>>();
    k_unpack<<<(PP+255)/256, 256>>>();
    k_impix<<<PP/4, 128>>>(sel_out);
    k_pcpoint<<<PP/4, 128>>>();
    k_mask<<<PP/32, 256>>>(0, mask_out, idx_out);
    k_mask<<<PP/32, 256>>>(1, mask_pc_out, idx_pc_out);
}

// round 4
// speedup vs baseline: 1.0001x; 1.0001x over previous
#include <cuda_runtime.h>

#define HH 40
#define WW 128
#define PP 5120
#define CC 128
#define KKN 25
#define SPOTN 5
#define NEGV (-1e8f)
#define FMAXV 3.402823466e38f

// ---------------- scratch (device globals; no allocations allowed) ----------
__device__ float g_nimf[PP*CC];
__device__ float g_npcf[PP*CC];
__device__ int   g_nb[PP*KKN];
__device__ unsigned long long g_rowbest[PP];
__device__ unsigned long long g_colbest[PP];
__device__ float g_imbs[PP];   // best_score per pixel
__device__ int   g_imbi[PP];   // best_index per pixel (pc idx)
__device__ float g_pcbs[PP];   // best_pc_score per point
__device__ int   g_pcbi[PP];   // best_pc_idx per point (pixel idx)
__device__ int   g_spot_im[PP*125];
__device__ int   g_spot_pc[PP*125];

__device__ __forceinline__ unsigned f2sort(float f){
    unsigned b = __float_as_uint(f);
    return (b & 0x80000000u) ? ~b : (b | 0x80000000u);
}
__device__ __forceinline__ float sort2f(unsigned u){
    unsigned b = (u & 0x80000000u) ? (u & 0x7fffffffu) : ~u;
    return __uint_as_float(b);
}
__device__ __forceinline__ int iclamp(int v, int lo, int hi){
    return v < lo ? lo : (v > hi ? hi : v);
}
__device__ __forceinline__ unsigned long long maxull(unsigned long long a, unsigned long long b){
    return a > b ? a : b;
}
__device__ __forceinline__ unsigned long long minull(unsigned long long a, unsigned long long b){
    return a < b ? a : b;
}
#define KEYPACK(v,n) ((((unsigned long long)f2sort(v)) << 32) | (unsigned)(~(n)))

// ---------------- K1: L2 normalize both feature sets ------------------------
__global__ __launch_bounds__(256) void k_norm(const float* __restrict__ imf,
                                              const float* __restrict__ pcf){
    int warp = (blockIdx.x*blockDim.x + threadIdx.x) >> 5;
    int lane = threadIdx.x & 31;
    if (warp >= 2*PP) return;
    const float* src = (warp < PP) ? imf : pcf;
    float* dst       = (warp < PP) ? g_nimf : g_npcf;
    int r = (warp < PP) ? warp : warp - PP;
    float4 v = ((const float4*)(src + (size_t)r*CC))[lane];
    float ss = v.x*v.x + v.y*v.y + v.z*v.z + v.w*v.w;
    #pragma unroll
    for (int o=16;o;o>>=1) ss += __shfl_xor_sync(0xffffffffu, ss, o);
    float inv = 1.0f / fmaxf(sqrtf(ss), 1e-12f);
    v.x*=inv; v.y*=inv; v.z*=inv; v.w*=inv;
    ((float4*)(dst + (size_t)r*CC))[lane] = v;
}

// ---------------- K2: init packed argmax accumulators -----------------------
__global__ void k_init(){
    int i = blockIdx.x*blockDim.x + threadIdx.x;
    if (i < PP){ g_rowbest[i] = 0ull; g_colbest[i] = 0ull; }
}

// ---------------- K3: knn (top-25 nearest, self first, tie->lower idx) ------
// 2 rows per block, 128 threads per row (40 KB smem < 48 KB static cap).
// Keys: (d2_bits<<32 | j); min-order == (d2 asc, idx asc) == top_k(-d2) order.
// Extraction order is globally ascending in key, so the owner's rescan just
// excludes key <= last extracted key; smem distances stay read-only after fill.
#define KNN_ROWS 2
#define KNN_TPR  128
__global__ __launch_bounds__(256) void k_knn(const float* __restrict__ pts){
    __shared__ float sd[KNN_ROWS][PP];                 // 40 KB
    __shared__ unsigned long long wmin[KNN_ROWS][4];
    __shared__ unsigned long long best[KNN_ROWS];
    int tid  = threadIdx.x;
    int g    = tid >> 7;          // row within block (0..1)
    int sub  = tid & 127;         // thread within row
    int lane = tid & 31;
    int wig  = (tid >> 5) & 3;    // warp within row group (0..3)
    int i = blockIdx.x*KNN_ROWS + g;
    float px = pts[i*3+0], py = pts[i*3+1], pz = pts[i*3+2];

    unsigned long long lmin = ~0ull;
    for (int j = sub; j < PP; j += KNN_TPR){
        float dx = pts[j*3+0]-px, dy = pts[j*3+1]-py, dz = pts[j*3+2]-pz;
        float d2 = fmaf(dx,dx, fmaf(dy,dy, dz*dz));    // >=0: bit order == numeric
        sd[g][j] = d2;
        unsigned long long key = ((unsigned long long)__float_as_uint(d2) << 32) | (unsigned)j;
        lmin = minull(lmin, key);
    }

    for (int t=0; t<KKN; t++){
        // warp reduce -> 4 warp minima per row -> scalar combine; 2 barriers
        unsigned long long tmp = lmin;
        #pragma unroll
        for (int o=16;o;o>>=1) tmp = minull(tmp, __shfl_xor_sync(0xffffffffu, tmp, o));
        if (lane == 0) wmin[g][wig] = tmp;
        __syncthreads();
        if (sub == 0){
            unsigned long long m = minull(minull(wmin[g][0], wmin[g][1]),
                                          minull(wmin[g][2], wmin[g][3]));
            best[g] = m;
            g_nb[i*KKN + t] = (int)(unsigned)m;
        }
        __syncthreads();
        unsigned long long b = best[g];
        int j = (int)(unsigned)b;
        if ((j & 127) == sub){
            // rescan own stripe (40 elems), excluding already-extracted (key <= b)
            unsigned long long nm = ~0ull;
            #pragma unroll 4
            for (int jj = sub; jj < PP; jj += KNN_TPR){
                unsigned long long key = ((unsigned long long)__float_as_uint(sd[g][jj]) << 32) | (unsigned)jj;
                if (key > b) nm = minull(nm, key);
            }
            lmin = nm;
        }
    }
}

// ---------------- K4: fused GEMM + row/col argmax ----------------------------
// S[p][n] = dot(nimf[p], npcf[n]); row max -> g_rowbest, col max -> g_colbest.
// Accumulators are 16 NAMED float4 registers (no local arrays, no address-of).
#define FOR_ROWS(OP) OP(0,d0a,d0b) OP(1,d1a,d1b) OP(2,d2a,d2b) OP(3,d3a,d3b) \
                     OP(4,d4a,d4b) OP(5,d5a,d5b) OP(6,d6a,d6b) OP(7,d7a,d7b)
#define DECL_ROW(r,A,B) float4 A = {0.f,0.f,0.f,0.f}; float4 B = {0.f,0.f,0.f,0.f};
#define AV0 a0.x
#define AV1 a0.y
#define AV2 a0.z
#define AV3 a0.w
#define AV4 a1.x
#define AV5 a1.y
#define AV6 a1.z
#define AV7 a1.w
#define FMA_ROW(r,A,B) { float av_ = AV##r; \
    A.x = fmaf(av_, b0.x, A.x); A.y = fmaf(av_, b0.y, A.y); \
    A.z = fmaf(av_, b0.z, A.z); A.w = fmaf(av_, b0.w, A.w); \
    B.x = fmaf(av_, b1.x, B.x); B.y = fmaf(av_, b1.y, B.y); \
    B.z = fmaf(av_, b1.z, B.z); B.w = fmaf(av_, b1.w, B.w); }
#define ROW_ST(r,A,B) { int n0_ = c0 + tx*8; \
    unsigned long long bb_ = KEYPACK(A.x, n0_); \
    bb_ = maxull(bb_, KEYPACK(A.y, n0_+1)); bb_ = maxull(bb_, KEYPACK(A.z, n0_+2)); \
    bb_ = maxull(bb_, KEYPACK(A.w, n0_+3)); bb_ = maxull(bb_, KEYPACK(B.x, n0_+4)); \
    bb_ = maxull(bb_, KEYPACK(B.y, n0_+5)); bb_ = maxull(bb_, KEYPACK(B.z, n0_+6)); \
    bb_ = maxull(bb_, KEYPACK(B.w, n0_+7)); \
    red[(ty*8+r)*16 + tx] = bb_; }
#define COL_UPD(r,A,B) { int m_ = r0 + ty*8 + r; \
    e0 = maxull(e0, KEYPACK(A.x, m_)); e1 = maxull(e1, KEYPACK(A.y, m_)); \
    e2 = maxull(e2, KEYPACK(A.z, m_)); e3 = maxull(e3, KEYPACK(A.w, m_)); \
    e4 = maxull(e4, KEYPACK(B.x, m_)); e5 = maxull(e5, KEYPACK(B.y, m_)); \
    e6 = maxull(e6, KEYPACK(B.z, m_)); e7 = maxull(e7, KEYPACK(B.w, m_)); }

__global__ __launch_bounds__(256) void k_gemm(){
    __shared__ __align__(16) char smem_raw[2*32*132*4];  // 33792 B
    float (*As)[132] = (float (*)[132])smem_raw;
    float (*Bs)[132] = (float (*)[132])(smem_raw + 32*132*4);
    int tid = threadIdx.x;
    int tx = tid & 15, ty = tid >> 4;
    int r0 = blockIdx.y*128, c0 = blockIdx.x*128;
    FOR_ROWS(DECL_ROW)

    for (int kc=0; kc<CC; kc+=32){
        #pragma unroll
        for (int it=0; it<4; ++it){
            int idx = it*256 + tid;
            int row = idx >> 3;
            int k4  = (idx & 7)*4;
            float4 a = *(const float4*)&g_nimf[(size_t)(r0+row)*CC + kc + k4];
            As[k4+0][row]=a.x; As[k4+1][row]=a.y; As[k4+2][row]=a.z; As[k4+3][row]=a.w;
            float4 b = *(const float4*)&g_npcf[(size_t)(c0+row)*CC + kc + k4];
            Bs[k4+0][row]=b.x; Bs[k4+1][row]=b.y; Bs[k4+2][row]=b.z; Bs[k4+3][row]=b.w;
        }
        __syncthreads();
        #pragma unroll 8
        for (int k=0; k<32; k++){
            float4 a0 = *(const float4*)&As[k][ty*8+0];
            float4 a1 = *(const float4*)&As[k][ty*8+4];
            float4 b0 = *(const float4*)&Bs[k][tx*8+0];
            float4 b1 = *(const float4*)&Bs[k][tx*8+4];
            FOR_ROWS(FMA_ROW)
        }
        __syncthreads();
    }

    unsigned long long* red = (unsigned long long*)smem_raw;  // 2048 entries
    // ---- row argmax (index = point n, tie -> lower n) ----
    FOR_ROWS(ROW_ST)
    __syncthreads();
    if (tid < 128){
        unsigned long long b = 0ull;
        #pragma unroll
        for (int t=0;t<16;t++) b = maxull(b, red[tid*16+t]);
        atomicMax(&g_rowbest[r0+tid], b);
    }
    __syncthreads();
    // ---- col argmax (index = pixel p, tie -> lower p) ----
    unsigned long long e0=0,e1=0,e2=0,e3=0,e4=0,e5=0,e6=0,e7=0;
    FOR_ROWS(COL_UPD)
    red[(tx*8+0)*16 + ty] = e0;
    red[(tx*8+1)*16 + ty] = e1;
    red[(tx*8+2)*16 + ty] = e2;
    red[(tx*8+3)*16 + ty] = e3;
    red[(tx*8+4)*16 + ty] = e4;
    red[(tx*8+5)*16 + ty] = e5;
    red[(tx*8+6)*16 + ty] = e6;
    red[(tx*8+7)*16 + ty] = e7;
    __syncthreads();
    if (tid < 128){
        unsigned long long b = 0ull;
        #pragma unroll
        for (int t=0;t<16;t++) b = maxull(b, red[tid*16+t]);
        atomicMax(&g_colbest[c0+tid], b);
    }
}

// ---------------- K5: unpack packed argmax ----------------------------------
__global__ void k_unpack(){
    int i = blockIdx.x*blockDim.x + threadIdx.x;
    if (i >= PP) return;
    unsigned long long k1 = g_rowbest[i];
    g_imbs[i] = sort2f((unsigned)(k1 >> 32));
    g_imbi[i] = (int)(~(unsigned)k1);
    unsigned long long k2 = g_colbest[i];
    g_pcbs[i] = sort2f((unsigned)(k2 >> 32));
    g_pcbi[i] = (int)(~(unsigned)k2);
}

// ---------------- K6: im branch: sims, softmax, select out, top-4, spot -----
__global__ __launch_bounds__(128) void k_impix(float* __restrict__ sel_out){
    int warp = (blockIdx.x*blockDim.x + threadIdx.x) >> 5;
    int lane = threadIdx.x & 31;
    if (warp >= PP) return;
    int p = warp, h = p >> 7, w = p & 127;   // WW == 128
    float4 cf = ((const float4*)(g_nimf + (size_t)p*CC))[lane];

    float myval = 0.f;
    #pragma unroll 1
    for (int k=0; k<KKN; k++){
        int di = k/5 - 2, dj = k%5 - 2;
        int hh = iclamp(h+di, 0, HH-1), ww = iclamp(w+dj, 0, WW-1);
        float4 nf = ((const float4*)(g_nimf + (size_t)(hh*WW+ww)*CC))[lane];
        float s = cf.x*nf.x + cf.y*nf.y + cf.z*nf.z + cf.w*nf.w;
        #pragma unroll
        for (int o=16;o;o>>=1) s += __shfl_xor_sync(0xffffffffu, s, o);
        if (lane == k) myval = s;
    }
    // softmax over lanes 0..24
    float v = (lane < KKN) ? myval : -FMAXV;
    float m = v;
    #pragma unroll
    for (int o=16;o;o>>=1) m = fmaxf(m, __shfl_xor_sync(0xffffffffu, m, o));
    float e = (lane < KKN) ? expf(v - m) : 0.f;
    float su = e;
    #pragma unroll
    for (int o=16;o;o>>=1) su += __shfl_xor_sync(0xffffffffu, su, o);
    float soft = e / su;

    int di = lane/5 - 2, dj = lane%5 - 2;
    float selv = NEGV;
    if (lane < KKN){
        bool inb = ((unsigned)(h+di) < (unsigned)HH) && ((unsigned)(w+dj) < (unsigned)WW);
        int hh = iclamp(h+di, 0, HH-1), ww = iclamp(w+dj, 0, WW-1);
        float conf = g_imbs[hh*WW+ww];
        selv = inb ? soft*conf : NEGV;
        sel_out[(size_t)lane*PP + p] = selv;
    }
    // seeding: center (k=12) then top-4 excluding center; process immediately
    float cand = (lane < KKN && lane != 12) ? selv : -FMAXV;
    #pragma unroll 1
    for (int s=0; s<SPOTN; s++){
        int kk;
        if (s == 0){
            kk = 12;
        } else {
            unsigned long long key = ((unsigned long long)f2sort(cand) << 32) | (unsigned)(31 - lane);
            #pragma unroll
            for (int o=16;o;o>>=1){
                unsigned long long ok = __shfl_xor_sync(0xffffffffu, key, o);
                if (ok > key) key = ok;
            }
            kk = 31 - (int)(key & 0xffffffffull);
            if (lane == kk) cand = -FMAXV;
        }
        int q = (h + kk/5 - 2)*WW + (w + kk%5 - 2);  // selected are always in-bounds
        int sd = g_imbi[q];
        if (lane < KKN) g_spot_im[(size_t)p*125 + s*25 + lane] = g_nb[sd*KKN + lane];
    }
}

// ---------------- K7: pc branch ---------------------------------------------
__global__ __launch_bounds__(128) void k_pcpoint(){
    int warp = (blockIdx.x*blockDim.x + threadIdx.x) >> 5;
    int lane = threadIdx.x & 31;
    if (warp >= PP) return;
    int p = warp;
    float4 cf = ((const float4*)(g_npcf + (size_t)p*CC))[lane];

    float myval = 0.f; int myq = 0;
    #pragma unroll 1
    for (int k=0; k<KKN; k++){
        int q = g_nb[p*KKN + k];
        float4 nf = ((const float4*)(g_npcf + (size_t)q*CC))[lane];
        float s = cf.x*nf.x + cf.y*nf.y + cf.z*nf.z + cf.w*nf.w;
        #pragma unroll
        for (int o=16;o;o>>=1) s += __shfl_xor_sync(0xffffffffu, s, o);
        if (lane == k){ myval = s; myq = q; }
    }
    float v = (lane < KKN) ? myval : -FMAXV;
    float m = v;
    #pragma unroll
    for (int o=16;o;o>>=1) m = fmaxf(m, __shfl_xor_sync(0xffffffffu, m, o));
    float e = (lane < KKN) ? expf(v - m) : 0.f;
    float su = e;
    #pragma unroll
    for (int o=16;o;o>>=1) su += __shfl_xor_sync(0xffffffffu, su, o);
    float soft = e / su;

    float selv = NEGV;
    if (lane < KKN) selv = (lane == 0) ? NEGV : soft * g_pcbs[myq];
    float cand = (lane >= 1 && lane < KKN) ? selv : -FMAXV;
    #pragma unroll 1
    for (int s=0; s<SPOTN; s++){
        int kk;
        if (s == 0){
            kk = 0;
        } else {
            unsigned long long key = ((unsigned long long)f2sort(cand) << 32) | (unsigned)(31 - lane);
            #pragma unroll
            for (int o=16;o;o>>=1){
                unsigned long long ok = __shfl_xor_sync(0xffffffffu, key, o);
                if (ok > key) key = ok;
            }
            kk = 31 - (int)(key & 0xffffffffull);
            if (lane == kk) cand = -FMAXV;
        }
        int qq = __shfl_sync(0xffffffffu, myq, kk);
        int pix = g_pcbi[qq];
        int pr = pix >> 7, pc = pix & 127;
        if (lane < KKN){
            int rr = iclamp(pr + lane/5 - 2, 0, HH-1);
            int cc = iclamp(pc + lane%5 - 2, 0, WW-1);
            g_spot_pc[(size_t)p*125 + s*25 + lane] = rr*WW + cc;
        }
    }
}

// ---------------- K8: scatter mask + stable top-125 (bitmask scan) ----------
// which: 0 -> g_spot_im, 1 -> g_spot_pc (device-global pointers bound in-kernel)
__global__ __launch_bounds__(256) void k_mask(int which,
                                              float* __restrict__ omask,
                                              float* __restrict__ oidx){
    __shared__ unsigned bm[32][160];   // 32 rows x 5120 bits
    const int* spot = which ? g_spot_pc : g_spot_im;
    int r0 = blockIdx.x*32;
    int tid = threadIdx.x;
    for (int i=tid; i<32*160; i+=256) ((unsigned*)bm)[i] = 0u;
    __syncthreads();
    for (int e=tid; e<32*125; e+=256){
        int row = e / 125;
        int v = spot[(size_t)(r0+row)*125 + (e % 125)];
        atomicOr(&bm[row][v>>5], 1u << (v & 31));
    }
    __syncthreads();
    if (tid < 32){
        int row = tid, t = 0;
        float* om = omask + (size_t)(r0+row)*125;
        float* oi = oidx  + (size_t)(r0+row)*125;
        for (int w2=0; w2<160; w2++){
            unsigned x = bm[row][w2];
            while (x){
                int b = __ffs(x) - 1; x &= x - 1;
                oi[t] = (float)(w2*32 + b); om[t] = 1.f; t++;
            }
        }
        for (int j=0; t<125; j++){
            if (!((bm[row][j>>5] >> (j&31)) & 1u)){
                oi[t] = (float)j; om[t] = 0.f; t++;
            }
        }
    }
}

// ---------------- launch ------------------------------------------------------
extern "C" void kernel_launch(void* const* d_in, const int* in_sizes, int n_in,
                              void* d_out, int out_size){
    const float* imf = (const float*)d_in[0];
    const float* pcf = (const float*)d_in[1];
    const float* pts = (const float*)d_in[2];
    float* out = (float*)d_out;

    float* sel_out     = out;                       // 25*5120
    float* mask_out    = out + 25*PP;               // 5120*125
    float* idx_out     = out + 25*PP + 125*PP;      // 5120*125
    float* idx_pc_out  = out + 25*PP + 2*125*PP;    // 5120*125
    float* mask_pc_out = out + 25*PP + 3*125*PP;    // 5120*125

    k_norm<<<(2*PP*32 + 255)/256, 256>>>(imf, pcf);
    k_init<<<(PP+255)/256, 256>>>();
    k_knn<<<PP/KNN_ROWS, 256>>>(pts);
    dim3 gg(PP/128, PP/128);
    k_gemm<<<gg, 256>>>();
    k_unpack<<<(PP+255)/256, 256>>>();
    k_impix<<<PP/4, 128>>>(sel_out);
    k_pcpoint<<<PP/4, 128>>>();
    k_mask<<<PP/32, 256>>>(0, mask_out, idx_out);
    k_mask<<<PP/32, 256>>>(1, mask_pc_out, idx_pc_out);
}

// round 5
// speedup vs baseline: 1.0034x; 1.0033x over previous
#include <cuda_runtime.h>

#define HH 40
#define WW 128
#define PP 5120
#define CC 128
#define KKN 25
#define SPOTN 5
#define NEGV (-1e8f)
#define FMAXV 3.402823466e38f

// ---------------- scratch (device globals; no allocations allowed) ----------
__device__ float g_nimf[PP*CC];
__device__ float g_npcf[PP*CC];
__device__ int   g_nb[PP*KKN];
__device__ unsigned long long g_rowbest[PP];
__device__ unsigned long long g_colbest[PP];
__device__ float g_imbs[PP];   // best_score per pixel
__device__ int   g_imbi[PP];   // best_index per pixel (pc idx)
__device__ float g_pcbs[PP];   // best_pc_score per point
__device__ int   g_pcbi[PP];   // best_pc_idx per point (pixel idx)
__device__ int   g_spot_im[PP*125];
__device__ int   g_spot_pc[PP*125];

__device__ __forceinline__ unsigned f2sort(float f){
    unsigned b = __float_as_uint(f);
    return (b & 0x80000000u) ? ~b : (b | 0x80000000u);
}
__device__ __forceinline__ float sort2f(unsigned u){
    unsigned b = (u & 0x80000000u) ? (u & 0x7fffffffu) : ~u;
    return __uint_as_float(b);
}
__device__ __forceinline__ int iclamp(int v, int lo, int hi){
    return v < lo ? lo : (v > hi ? hi : v);
}
__device__ __forceinline__ unsigned long long maxull(unsigned long long a, unsigned long long b){
    return a > b ? a : b;
}
__device__ __forceinline__ unsigned long long minull(unsigned long long a, unsigned long long b){
    return a < b ? a : b;
}
#define KEYPACK(v,n) ((((unsigned long long)f2sort(v)) << 32) | (unsigned)(~(n)))

// ---------------- K1: L2 normalize both feature sets ------------------------
__global__ __launch_bounds__(256) void k_norm(const float* __restrict__ imf,
                                              const float* __restrict__ pcf){
    int warp = (blockIdx.x*blockDim.x + threadIdx.x) >> 5;
    int lane = threadIdx.x & 31;
    if (warp >= 2*PP) return;
    const float* src = (warp < PP) ? imf : pcf;
    float* dst       = (warp < PP) ? g_nimf : g_npcf;
    int r = (warp < PP) ? warp : warp - PP;
    float4 v = ((const float4*)(src + (size_t)r*CC))[lane];
    float ss = v.x*v.x + v.y*v.y + v.z*v.z + v.w*v.w;
    #pragma unroll
    for (int o=16;o;o>>=1) ss += __shfl_xor_sync(0xffffffffu, ss, o);
    float inv = 1.0f / fmaxf(sqrtf(ss), 1e-12f);
    v.x*=inv; v.y*=inv; v.z*=inv; v.w*=inv;
    ((float4*)(dst + (size_t)r*CC))[lane] = v;
}

// ---------------- K2: init packed argmax accumulators -----------------------
__global__ void k_init(){
    int i = blockIdx.x*blockDim.x + threadIdx.x;
    if (i < PP){ g_rowbest[i] = 0ull; g_colbest[i] = 0ull; }
}

// ---------------- K3: knn (top-25 nearest, self first, tie->lower idx) ------
// 2 rows per block, 128 threads per row (40 KB smem < 48 KB static cap).
// Keys: (d2_bits<<32 | j); min-order == (d2 asc, idx asc) == top_k(-d2) order.
// Extraction order is globally ascending in key, so the owner's rescan just
// excludes key <= last extracted key; smem distances stay read-only after fill.
#define KNN_ROWS 2
#define KNN_TPR  128
__global__ __launch_bounds__(256) void k_knn(const float* __restrict__ pts){
    __shared__ float sd[KNN_ROWS][PP];                 // 40 KB
    __shared__ unsigned long long wmin[KNN_ROWS][4];
    __shared__ unsigned long long best[KNN_ROWS];
    int tid  = threadIdx.x;
    int g    = tid >> 7;          // row within block (0..1)
    int sub  = tid & 127;         // thread within row
    int lane = tid & 31;
    int wig  = (tid >> 5) & 3;    // warp within row group (0..3)
    int i = blockIdx.x*KNN_ROWS + g;
    float px = pts[i*3+0], py = pts[i*3+1], pz = pts[i*3+2];

    unsigned long long lmin = ~0ull;
    for (int j = sub; j < PP; j += KNN_TPR){
        float dx = pts[j*3+0]-px, dy = pts[j*3+1]-py, dz = pts[j*3+2]-pz;
        float d2 = fmaf(dx,dx, fmaf(dy,dy, dz*dz));    // >=0: bit order == numeric
        sd[g][j] = d2;
        unsigned long long key = ((unsigned long long)__float_as_uint(d2) << 32) | (unsigned)j;
        lmin = minull(lmin, key);
    }

    for (int t=0; t<KKN; t++){
        // warp reduce -> 4 warp minima per row -> scalar combine; 2 barriers
        unsigned long long tmp = lmin;
        #pragma unroll
        for (int o=16;o;o>>=1) tmp = minull(tmp, __shfl_xor_sync(0xffffffffu, tmp, o));
        if (lane == 0) wmin[g][wig] = tmp;
        __syncthreads();
        if (sub == 0){
            unsigned long long m = minull(minull(wmin[g][0], wmin[g][1]),
                                          minull(wmin[g][2], wmin[g][3]));
            best[g] = m;
            g_nb[i*KKN + t] = (int)(unsigned)m;
        }
        __syncthreads();
        unsigned long long b = best[g];
        int j = (int)(unsigned)b;
        if ((j & 127) == sub){
            // rescan own stripe (40 elems), excluding already-extracted (key <= b)
            unsigned long long nm = ~0ull;
            #pragma unroll 4
            for (int jj = sub; jj < PP; jj += KNN_TPR){
                unsigned long long key = ((unsigned long long)__float_as_uint(sd[g][jj]) << 32) | (unsigned)jj;
                if (key > b) nm = minull(nm, key);
            }
            lmin = nm;
        }
    }
}

// ---------------- K4: fused GEMM + row/col argmax ----------------------------
// S[p][n] = dot(nimf[p], npcf[n]); row max -> g_rowbest, col max -> g_colbest.
// Accumulators are 16 NAMED float4 registers (no local arrays, no address-of).
#define FOR_ROWS(OP) OP(0,d0a,d0b) OP(1,d1a,d1b) OP(2,d2a,d2b) OP(3,d3a,d3b) \
                     OP(4,d4a,d4b) OP(5,d5a,d5b) OP(6,d6a,d6b) OP(7,d7a,d7b)
#define DECL_ROW(r,A,B) float4 A = {0.f,0.f,0.f,0.f}; float4 B = {0.f,0.f,0.f,0.f};
#define AV0 a0.x
#define AV1 a0.y
#define AV2 a0.z
#define AV3 a0.w
#define AV4 a1.x
#define AV5 a1.y
#define AV6 a1.z
#define AV7 a1.w
#define FMA_ROW(r,A,B) { float av_ = AV##r; \
    A.x = fmaf(av_, b0.x, A.x); A.y = fmaf(av_, b0.y, A.y); \
    A.z = fmaf(av_, b0.z, A.z); A.w = fmaf(av_, b0.w, A.w); \
    B.x = fmaf(av_, b1.x, B.x); B.y = fmaf(av_, b1.y, B.y); \
    B.z = fmaf(av_, b1.z, B.z); B.w = fmaf(av_, b1.w, B.w); }
#define ROW_ST(r,A,B) { int n0_ = c0 + tx*8; \
    unsigned long long bb_ = KEYPACK(A.x, n0_); \
    bb_ = maxull(bb_, KEYPACK(A.y, n0_+1)); bb_ = maxull(bb_, KEYPACK(A.z, n0_+2)); \
    bb_ = maxull(bb_, KEYPACK(A.w, n0_+3)); bb_ = maxull(bb_, KEYPACK(B.x, n0_+4)); \
    bb_ = maxull(bb_, KEYPACK(B.y, n0_+5)); bb_ = maxull(bb_, KEYPACK(B.z, n0_+6)); \
    bb_ = maxull(bb_, KEYPACK(B.w, n0_+7)); \
    red[(ty*8+r)*16 + tx] = bb_; }
#define COL_UPD(r,A,B) { int m_ = r0 + ty*8 + r; \
    e0 = maxull(e0, KEYPACK(A.x, m_)); e1 = maxull(e1, KEYPACK(A.y, m_)); \
    e2 = maxull(e2, KEYPACK(A.z, m_)); e3 = maxull(e3, KEYPACK(A.w, m_)); \
    e4 = maxull(e4, KEYPACK(B.x, m_)); e5 = maxull(e5, KEYPACK(B.y, m_)); \
    e6 = maxull(e6, KEYPACK(B.z, m_)); e7 = maxull(e7, KEYPACK(B.w, m_)); }

__global__ __launch_bounds__(256) void k_gemm(){
    __shared__ __align__(16) char smem_raw[2*32*132*4];  // 33792 B
    float (*As)[132] = (float (*)[132])smem_raw;
    float (*Bs)[132] = (float (*)[132])(smem_raw + 32*132*4);
    int tid = threadIdx.x;
    int tx = tid & 15, ty = tid >> 4;
    int r0 = blockIdx.y*128, c0 = blockIdx.x*128;
    FOR_ROWS(DECL_ROW)

    for (int kc=0; kc<CC; kc+=32){
        #pragma unroll
        for (int it=0; it<4; ++it){
            int idx = it*256 + tid;
            int row = idx >> 3;
            int k4  = (idx & 7)*4;
            float4 a = *(const float4*)&g_nimf[(size_t)(r0+row)*CC + kc + k4];
            As[k4+0][row]=a.x; As[k4+1][row]=a.y; As[k4+2][row]=a.z; As[k4+3][row]=a.w;
            float4 b = *(const float4*)&g_npcf[(size_t)(c0+row)*CC + kc + k4];
            Bs[k4+0][row]=b.x; Bs[k4+1][row]=b.y; Bs[k4+2][row]=b.z; Bs[k4+3][row]=b.w;
        }
        __syncthreads();
        #pragma unroll 8
        for (int k=0; k<32; k++){
            float4 a0 = *(const float4*)&As[k][ty*8+0];
            float4 a1 = *(const float4*)&As[k][ty*8+4];
            float4 b0 = *(const float4*)&Bs[k][tx*8+0];
            float4 b1 = *(const float4*)&Bs[k][tx*8+4];
            FOR_ROWS(FMA_ROW)
        }
        __syncthreads();
    }

    unsigned long long* red = (unsigned long long*)smem_raw;  // 2048 entries
    // ---- row argmax (index = point n, tie -> lower n) ----
    FOR_ROWS(ROW_ST)
    __syncthreads();
    if (tid < 128){
        unsigned long long b = 0ull;
        #pragma unroll
        for (int t=0;t<16;t++) b = maxull(b, red[tid*16+t]);
        atomicMax(&g_rowbest[r0+tid], b);
    }
    __syncthreads();
    // ---- col argmax (index = pixel p, tie -> lower p) ----
    unsigned long long e0=0,e1=0,e2=0,e3=0,e4=0,e5=0,e6=0,e7=0;
    FOR_ROWS(COL_UPD)
    red[(tx*8+0)*16 + ty] = e0;
    red[(tx*8+1)*16 + ty] = e1;
    red[(tx*8+2)*16 + ty] = e2;
    red[(tx*8+3)*16 + ty] = e3;
    red[(tx*8+4)*16 + ty] = e4;
    red[(tx*8+5)*16 + ty] = e5;
    red[(tx*8+6)*16 + ty] = e6;
    red[(tx*8+7)*16 + ty] = e7;
    __syncthreads();
    if (tid < 128){
        unsigned long long b = 0ull;
        #pragma unroll
        for (int t=0;t<16;t++) b = maxull(b, red[tid*16+t]);
        atomicMax(&g_colbest[c0+tid], b);
    }
}

// ---------------- K5: unpack packed argmax ----------------------------------
__global__ void k_unpack(){
    int i = blockIdx.x*blockDim.x + threadIdx.x;
    if (i >= PP) return;
    unsigned long long k1 = g_rowbest[i];
    g_imbs[i] = sort2f((unsigned)(k1 >> 32));
    g_imbi[i] = (int)(~(unsigned)k1);
    unsigned long long k2 = g_colbest[i];
    g_pcbs[i] = sort2f((unsigned)(k2 >> 32));
    g_pcbi[i] = (int)(~(unsigned)k2);
}

// ---------------- K6: im branch: sims, softmax, select out, top-4, spot -----
__global__ __launch_bounds__(128) void k_impix(float* __restrict__ sel_out){
    int warp = (blockIdx.x*blockDim.x + threadIdx.x) >> 5;
    int lane = threadIdx.x & 31;
    if (warp >= PP) return;
    int p = warp, h = p >> 7, w = p & 127;   // WW == 128
    float4 cf = ((const float4*)(g_nimf + (size_t)p*CC))[lane];

    float myval = 0.f;
    #pragma unroll 1
    for (int k=0; k<KKN; k++){
        int di = k/5 - 2, dj = k%5 - 2;
        int hh = iclamp(h+di, 0, HH-1), ww = iclamp(w+dj, 0, WW-1);
        float4 nf = ((const float4*)(g_nimf + (size_t)(hh*WW+ww)*CC))[lane];
        float s = cf.x*nf.x + cf.y*nf.y + cf.z*nf.z + cf.w*nf.w;
        #pragma unroll
        for (int o=16;o;o>>=1) s += __shfl_xor_sync(0xffffffffu, s, o);
        if (lane == k) myval = s;
    }
    // softmax over lanes 0..24
    float v = (lane < KKN) ? myval : -FMAXV;
    float m = v;
    #pragma unroll
    for (int o=16;o;o>>=1) m = fmaxf(m, __shfl_xor_sync(0xffffffffu, m, o));
    float e = (lane < KKN) ? expf(v - m) : 0.f;
    float su = e;
    #pragma unroll
    for (int o=16;o;o>>=1) su += __shfl_xor_sync(0xffffffffu, su, o);
    float soft = e / su;

    int di = lane/5 - 2, dj = lane%5 - 2;
    float selv = NEGV;
    if (lane < KKN){
        bool inb = ((unsigned)(h+di) < (unsigned)HH) && ((unsigned)(w+dj) < (unsigned)WW);
        int hh = iclamp(h+di, 0, HH-1), ww = iclamp(w+dj, 0, WW-1);
        float conf = g_imbs[hh*WW+ww];
        selv = inb ? soft*conf : NEGV;
        sel_out[(size_t)lane*PP + p] = selv;
    }
    // seeding: center (k=12) then top-4 excluding center; process immediately
    float cand = (lane < KKN && lane != 12) ? selv : -FMAXV;
    #pragma unroll 1
    for (int s=0; s<SPOTN; s++){
        int kk;
        if (s == 0){
            kk = 12;
        } else {
            unsigned long long key = ((unsigned long long)f2sort(cand) << 32) | (unsigned)(31 - lane);
            #pragma unroll
            for (int o=16;o;o>>=1){
                unsigned long long ok = __shfl_xor_sync(0xffffffffu, key, o);
                if (ok > key) key = ok;
            }
            kk = 31 - (int)(key & 0xffffffffull);
            if (lane == kk) cand = -FMAXV;
        }
        int q = (h + kk/5 - 2)*WW + (w + kk%5 - 2);  // selected are always in-bounds
        int sd = g_imbi[q];
        if (lane < KKN) g_spot_im[(size_t)p*125 + s*25 + lane] = g_nb[sd*KKN + lane];
    }
}

// ---------------- K7: pc branch ---------------------------------------------
__global__ __launch_bounds__(128) void k_pcpoint(){
    int warp = (blockIdx.x*blockDim.x + threadIdx.x) >> 5;
    int lane = threadIdx.x & 31;
    if (warp >= PP) return;
    int p = warp;
    float4 cf = ((const float4*)(g_npcf + (size_t)p*CC))[lane];

    float myval = 0.f; int myq = 0;
    #pragma unroll 1
    for (int k=0; k<KKN; k++){
        int q = g_nb[p*KKN + k];
        float4 nf = ((const float4*)(g_npcf + (size_t)q*CC))[lane];
        float s = cf.x*nf.x + cf.y*nf.y + cf.z*nf.z + cf.w*nf.w;
        #pragma unroll
        for (int o=16;o;o>>=1) s += __shfl_xor_sync(0xffffffffu, s, o);
        if (lane == k){ myval = s; myq = q; }
    }
    float v = (lane < KKN) ? myval : -FMAXV;
    float m = v;
    #pragma unroll
    for (int o=16;o;o>>=1) m = fmaxf(m, __shfl_xor_sync(0xffffffffu, m, o));
    float e = (lane < KKN) ? expf(v - m) : 0.f;
    float su = e;
    #pragma unroll
    for (int o=16;o;o>>=1) su += __shfl_xor_sync(0xffffffffu, su, o);
    float soft = e / su;

    float selv = NEGV;
    if (lane < KKN) selv = (lane == 0) ? NEGV : soft * g_pcbs[myq];
    float cand = (lane >= 1 && lane < KKN) ? selv : -FMAXV;
    #pragma unroll 1
    for (int s=0; s<SPOTN; s++){
        int kk;
        if (s == 0){
            kk = 0;
        } else {
            unsigned long long key = ((unsigned long long)f2sort(cand) << 32) | (unsigned)(31 - lane);
            #pragma unroll
            for (int o=16;o;o>>=1){
                unsigned long long ok = __shfl_xor_sync(0xffffffffu, key, o);
                if (ok > key) key = ok;
            }
            kk = 31 - (int)(key & 0xffffffffull);
            if (lane == kk) cand = -FMAXV;
        }
        int qq = __shfl_sync(0xffffffffu, myq, kk);
        int pix = g_pcbi[qq];
        int pr = pix >> 7, pc = pix & 127;
        if (lane < KKN){
            int rr = iclamp(pr + lane/5 - 2, 0, HH-1);
            int cc = iclamp(pc + lane%5 - 2, 0, WW-1);
            g_spot_pc[(size_t)p*125 + s*25 + lane] = rr*WW + cc;
        }
    }
}

// ---------------- K8: scatter mask + stable top-125 (bitmask scan) ----------
// which: 0 -> g_spot_im, 1 -> g_spot_pc (device-global pointers bound in-kernel)
__global__ __launch_bounds__(256) void k_mask(int which,
                                              float* __restrict__ omask,
                                              float* __restrict__ oidx){
    __shared__ unsigned bm[32][160];   // 32 rows x 5120 bits
    const int* spot = which ? g_spot_pc : g_spot_im;
    int r0 = blockIdx.x*32;
    int tid = threadIdx.x;
    for (int i=tid; i<32*160; i+=256) ((unsigned*)bm)[i] = 0u;
    __syncthreads();
    for (int e=tid; e<32*125; e+=256){
        int row = e / 125;
        int v = spot[(size_t)(r0+row)*125 + (e % 125)];
        atomicOr(&bm[row][v>>5], 1u << (v & 31));
    }
    __syncthreads();
    if (tid < 32){
        int row = tid, t = 0;
        float* om = omask + (size_t)(r0+row)*125;
        float* oi = oidx  + (size_t)(r0+row)*125;
        for (int w2=0; w2<160; w2++){
            unsigned x = bm[row][w2];
            while (x){
                int b = __ffs(x) - 1; x &= x - 1;
                oi[t] = (float)(w2*32 + b); om[t] = 1.f; t++;
            }
        }
        for (int j=0; t<125; j++){
            if (!((bm[row][j>>5] >> (j&31)) & 1u)){
                oi[t] = (float)j; om[t] = 0.f; t++;
            }
        }
    }
}

// ---------------- launch ------------------------------------------------------
extern "C" void kernel_launch(void* const* d_in, const int* in_sizes, int n_in,
                              void* d_out, int out_size){
    const float* imf = (const float*)d_in[0];
    const float* pcf = (const float*)d_in[1];
    const float* pts = (const float*)d_in[2];
    float* out = (float*)d_out;

    float* sel_out     = out;                       // 25*5120
    float* mask_out    = out + 25*PP;               // 5120*125
    float* idx_out     = out + 25*PP + 125*PP;      // 5120*125
    float* idx_pc_out  = out + 25*PP + 2*125*PP;    // 5120*125
    float* mask_pc_out = out + 25*PP + 3*125*PP;    // 5120*125

    k_norm<<<(2*PP*32 + 255)/256, 256>>>(imf, pcf);
    k_init<<<(PP+255)/256, 256>>>();
    k_knn<<<PP/KNN_ROWS, 256>>>(pts);
    dim3 gg(PP/128, PP/128);
    k_gemm<<<gg, 256>>>();
    k_unpack<<<(PP+255)/256, 256>>>();
    k_impix<<<PP/4, 128>>>(sel_out);
    k_pcpoint<<<PP/4, 128>>>();
    k_mask<<<PP/32, 256>>>(0, mask_out, idx_out);
    k_mask<<<PP/32, 256>>>(1, mask_pc_out, idx_pc_out);
}